// round 2
// baseline (speedup 1.0000x reference)
#include <cuda_runtime.h>
#include <cstdint>

// Problem constants (fixed by the dataset)
#define NMAX 50000
#define CMAX 5000
#define DIN  128
#define DOUT 40     // 10 float4 per row

// Scratch (static device globals — no allocation allowed)
__device__ int   g_deg[NMAX];
__device__ float g_dinv[NMAX];
__device__ int   g_repflag[NMAX];
__device__ float g_y0[NMAX * DOUT];   // projected features x @ W^T
__device__ float g_h1[NMAX * DOUT];   // after hop 1
__device__ float g_h2[NMAX * DOUT];   // after hop 2 (only rep rows valid)
__device__ float g_lsm[CMAX * DOUT];  // per-cluster log-softmax rows

__device__ __forceinline__ void red_add_v4(float* p, float4 v) {
    asm volatile("red.global.add.v4.f32 [%0], {%1,%2,%3,%4};"
                 :: "l"(__cvta_generic_to_global(p)),
                    "f"(v.x), "f"(v.y), "f"(v.z), "f"(v.w)
                 : "memory");
}

// ---- 1) init: deg = 1 (self loop), rep_flag = 0 ----
__global__ void k_init(int n) {
    int v = blockIdx.x * blockDim.x + threadIdx.x;
    if (v >= n) return;
    g_deg[v] = 1;
    g_repflag[v] = 0;
}

// ---- 2) set rep flags ----
__global__ void k_setrep(const int* __restrict__ rep_idx, int c) {
    int i = blockIdx.x * blockDim.x + threadIdx.x;
    if (i >= c) return;
    g_repflag[rep_idx[i]] = 1;
}

// ---- 3) degree over dst ----
__global__ void k_deg(const int* __restrict__ dst, int e) {
    int i = blockIdx.x * blockDim.x + threadIdx.x;
    if (i >= e) return;
    atomicAdd(&g_deg[dst[i]], 1);
}

// ---- 4) dinv = rsqrt(deg) ----
__global__ void k_dinv(int n) {
    int v = blockIdx.x * blockDim.x + threadIdx.x;
    if (v >= n) return;
    g_dinv[v] = rsqrtf((float)g_deg[v]);
}

// ---- 5) projection y0 = x @ W^T, plus hop-1 self-loop init h1 = dinv^2 * y0 ----
__global__ void k_project(const float* __restrict__ x, const float* __restrict__ W, int n) {
    __shared__ float Ws[DOUT * DIN];   // 20.5 KB
    for (int i = threadIdx.x; i < DOUT * DIN; i += blockDim.x) Ws[i] = W[i];
    __syncthreads();
    int v = blockIdx.x * blockDim.x + threadIdx.x;
    if (v >= n) return;

    float acc[DOUT];
#pragma unroll
    for (int o = 0; o < DOUT; o++) acc[o] = 0.0f;

    const float4* xr = (const float4*)(x + (size_t)v * DIN);
#pragma unroll 8
    for (int k = 0; k < DIN / 4; k++) {
        float4 xv = xr[k];
#pragma unroll
        for (int o = 0; o < DOUT; o++) {
            // all threads read the same smem address -> broadcast, conflict-free
            float4 w = *(const float4*)&Ws[o * DIN + k * 4];
            acc[o] = fmaf(xv.x, w.x, fmaf(xv.y, w.y, fmaf(xv.z, w.z, fmaf(xv.w, w.w, acc[o]))));
        }
    }
    float di = g_dinv[v];
    float d2 = di * di;
    float4* y = (float4*)(g_y0 + v * DOUT);
    float4* h = (float4*)(g_h1 + v * DOUT);
#pragma unroll
    for (int j = 0; j < DOUT / 4; j++) {
        float4 a = make_float4(acc[4*j], acc[4*j+1], acc[4*j+2], acc[4*j+3]);
        y[j] = a;
        h[j] = make_float4(d2*a.x, d2*a.y, d2*a.z, d2*a.w);
    }
}

// ---- 6) hop 1 edge scatter: h1[dst] += dinv[s]*dinv[d] * y0[src] ----
__global__ void k_hop1(const int* __restrict__ src, const int* __restrict__ dst, int e) {
    int i = blockIdx.x * blockDim.x + threadIdx.x;
    if (i >= e) return;
    int s = src[i], d = dst[i];
    float nrm = g_dinv[s] * g_dinv[d];
    const float4* yr = (const float4*)(g_y0 + s * DOUT);
    float* hr = g_h1 + d * DOUT;
#pragma unroll
    for (int j = 0; j < DOUT / 4; j++) {
        float4 v = yr[j];
        v.x *= nrm; v.y *= nrm; v.z *= nrm; v.w *= nrm;
        red_add_v4(hr + 4 * j, v);
    }
}

// ---- 7) hop-2 self-loop init, only at rep nodes: h2 = dinv^2 * h1 ----
__global__ void k_inith2(int n) {
    int v = blockIdx.x * blockDim.x + threadIdx.x;
    if (v >= n) return;
    if (!g_repflag[v]) return;
    float di = g_dinv[v];
    float d2 = di * di;
    const float4* h1r = (const float4*)(g_h1 + v * DOUT);
    float4* h2r = (float4*)(g_h2 + v * DOUT);
#pragma unroll
    for (int j = 0; j < DOUT / 4; j++) {
        float4 a = h1r[j];
        h2r[j] = make_float4(d2*a.x, d2*a.y, d2*a.z, d2*a.w);
    }
}

// ---- 8) hop 2 edge scatter, only into rep dst ----
__global__ void k_hop2(const int* __restrict__ src, const int* __restrict__ dst, int e) {
    int i = blockIdx.x * blockDim.x + threadIdx.x;
    if (i >= e) return;
    int d = dst[i];
    if (!g_repflag[d]) return;
    int s = src[i];
    float nrm = g_dinv[s] * g_dinv[d];
    const float4* hr = (const float4*)(g_h1 + s * DOUT);
    float* h2r = g_h2 + d * DOUT;
#pragma unroll
    for (int j = 0; j < DOUT / 4; j++) {
        float4 v = hr[j];
        v.x *= nrm; v.y *= nrm; v.z *= nrm; v.w *= nrm;
        red_add_v4(h2r + 4 * j, v);
    }
}

// ---- 9) per-cluster: gather rep row, add bias, log_softmax ----
__global__ void k_lsm(const int* __restrict__ rep_idx, const float* __restrict__ b, int c) {
    int ci = blockIdx.x * blockDim.x + threadIdx.x;
    if (ci >= c) return;
    int r = rep_idx[ci];
    const float* row = g_h2 + r * DOUT;
    float vals[DOUT];
    float mx = -1e30f;
#pragma unroll
    for (int o = 0; o < DOUT; o++) {
        vals[o] = row[o] + b[o];
        mx = fmaxf(mx, vals[o]);
    }
    float s = 0.0f;
#pragma unroll
    for (int o = 0; o < DOUT; o++) s += expf(vals[o] - mx);
    float l = logf(s) + mx;
    float* out = g_lsm + ci * DOUT;
#pragma unroll
    for (int o = 0; o < DOUT; o++) out[o] = vals[o] - l;
}

// ---- 10) broadcast per-cluster rows to all nodes ----
__global__ void k_bcast(const int* __restrict__ cluster_index, float* __restrict__ out, int n) {
    int idx = blockIdx.x * blockDim.x + threadIdx.x;   // over n * 10 float4 chunks
    int total = n * (DOUT / 4);
    if (idx >= total) return;
    int i = idx / (DOUT / 4);
    int j = idx % (DOUT / 4);
    int c = cluster_index[i];
    ((float4*)out)[idx] = ((const float4*)g_lsm)[c * (DOUT / 4) + j];
}

extern "C" void kernel_launch(void* const* d_in, const int* in_sizes, int n_in,
                              void* d_out, int out_size) {
    const float* x       = (const float*)d_in[0];
    const int*   edge    = (const int*)d_in[1];
    const int*   cluster = (const int*)d_in[2];
    const int*   rep     = (const int*)d_in[3];
    const float* W       = (const float*)d_in[4];
    const float* b       = (const float*)d_in[5];
    float* out = (float*)d_out;

    int n = in_sizes[0] / DIN;
    int e = in_sizes[1] / 2;
    int c = in_sizes[3];
    const int* src = edge;
    const int* dst = edge + e;

    const int B = 256;
    k_init   <<<(n + B - 1) / B, B>>>(n);
    k_setrep <<<(c + B - 1) / B, B>>>(rep, c);
    k_deg    <<<(e + B - 1) / B, B>>>(dst, e);
    k_dinv   <<<(n + B - 1) / B, B>>>(n);
    k_project<<<(n + B - 1) / B, B>>>(x, W, n);
    k_hop1   <<<(e + B - 1) / B, B>>>(src, dst, e);
    k_inith2 <<<(n + B - 1) / B, B>>>(n);
    k_hop2   <<<(e + B - 1) / B, B>>>(src, dst, e);
    k_lsm    <<<(c + B - 1) / B, B>>>(rep, b, c);
    int tot = n * (DOUT / 4);
    k_bcast  <<<(tot + B - 1) / B, B>>>(cluster, out, n);
}